// round 4
// baseline (speedup 1.0000x reference)
#include <cuda_runtime.h>

// Two-pass order-preserving ROI point pooling.
//   prep:   pack points -> float4 scratch (sentinel padded), zero padded output
//   pass1:  per (chunk, anchor) match counts   (smem point broadcast, anchor/thread)
//   prefix: per-anchor exclusive scan over chunks; emit clamped counts
//   pass2:  re-scan, write matches at base offsets while slot < n

#define THREADS 256
#define CHUNK   1024
#define MAX_P   256
#define MAX_A   4096
#define MAX_NPAD (MAX_P * CHUNK)

__device__ float4 g_pts[MAX_NPAD];          // 4 MB packed/padded points
__device__ int    g_cnt[MAX_P * MAX_A];     // [chunk][anchor] match counts
__device__ int    g_off[MAX_P * MAX_A];     // [chunk][anchor] exclusive base offsets

// ---------------------------------------------------------------------------
__global__ void prep_kernel(const float* __restrict__ pts, int N, int Npad,
                            float* __restrict__ out, long long zelems) {
    long long tid    = (long long)blockIdx.x * blockDim.x + threadIdx.x;
    long long stride = (long long)gridDim.x * blockDim.x;

    for (long long j = tid; j < Npad; j += stride) {
        float4 v;
        if (j < (long long)N) {
            v.x = pts[3 * j + 0];
            v.y = pts[3 * j + 1];
            v.z = pts[3 * j + 2];
            v.w = 0.0f;
        } else {  // sentinel: never inside any box (z < 0)
            v.x = 3.0e38f; v.y = 3.0e38f; v.z = -1.0f; v.w = 0.0f;
        }
        g_pts[j] = v;
    }

    // zero the padded output region (coalesced, vectorized)
    long long z4 = zelems >> 2;
    float4* out4 = (float4*)out;
    for (long long j = tid; j < z4; j += stride)
        out4[j] = make_float4(0.f, 0.f, 0.f, 0.f);
    for (long long j = (z4 << 2) + tid; j < zelems; j += stride)
        out[j] = 0.0f;
}

// ---------------------------------------------------------------------------
__global__ __launch_bounds__(THREADS)
void count_kernel(const float* __restrict__ anchors, int A) {
    __shared__ float4 sm[CHUNK];
    const int c = blockIdx.x;                       // point chunk
    const int a = blockIdx.y * THREADS + threadIdx.x;  // anchor (one per thread)

    const float4* src = g_pts + (size_t)c * CHUNK;
    #pragma unroll
    for (int i = threadIdx.x; i < CHUNK; i += THREADS) sm[i] = src[i];
    __syncthreads();

    if (a >= A) return;

    const float cx = anchors[a * 6 + 0];
    const float cy = anchors[a * 6 + 1];
    const float w  = anchors[a * 6 + 3];
    const float l  = anchors[a * 6 + 4];
    const float h  = anchors[a * 6 + 5];
    const float x0 = cx - w * 0.5f, x1 = cx + w * 0.5f;
    const float y0 = cy - l * 0.5f, y1 = cy + l * 0.5f;

    int cnt = 0;
    #pragma unroll 8
    for (int i = 0; i < CHUNK; ++i) {
        const float4 p = sm[i];
        const bool in = (p.x >= x0) & (p.x <= x1) &
                        (p.y >= y0) & (p.y <= y1) &
                        (p.z >= 0.0f) & (p.z <= h);
        cnt += (int)in;
    }
    g_cnt[c * A + a] = cnt;
}

// ---------------------------------------------------------------------------
__global__ void prefix_kernel(int A, int P, int n,
                              float* __restrict__ out_counts, int write_counts) {
    const int a = blockIdx.x * blockDim.x + threadIdx.x;
    if (a >= A) return;
    int run = 0;
    for (int c = 0; c < P; ++c) {
        const int v = g_cnt[c * A + a];
        g_off[c * A + a] = run;
        run += v;
    }
    if (write_counts)
        out_counts[a] = (float)(run < n ? run : n);
}

// ---------------------------------------------------------------------------
__global__ __launch_bounds__(THREADS)
void write_kernel(const float* __restrict__ anchors, int A, int n,
                  float* __restrict__ out) {
    __shared__ float4 sm[CHUNK];
    const int c = blockIdx.x;
    const int a = blockIdx.y * THREADS + threadIdx.x;

    const float4* src = g_pts + (size_t)c * CHUNK;
    #pragma unroll
    for (int i = threadIdx.x; i < CHUNK; i += THREADS) sm[i] = src[i];
    __syncthreads();

    if (a >= A) return;

    int base = g_off[c * A + a];
    if (base >= n) return;   // nothing this chunk contributes can land in [0, n)

    const float cx = anchors[a * 6 + 0];
    const float cy = anchors[a * 6 + 1];
    const float w  = anchors[a * 6 + 3];
    const float l  = anchors[a * 6 + 4];
    const float h  = anchors[a * 6 + 5];
    const float x0 = cx - w * 0.5f, x1 = cx + w * 0.5f;
    const float y0 = cy - l * 0.5f, y1 = cy + l * 0.5f;

    float* __restrict__ aout = out + (size_t)a * n * 3;

    #pragma unroll 4
    for (int i = 0; i < CHUNK; ++i) {
        const float4 p = sm[i];
        const bool in = (p.x >= x0) & (p.x <= x1) &
                        (p.y >= y0) & (p.y <= y1) &
                        (p.z >= 0.0f) & (p.z <= h);
        if (in) {
            if (base < n) {
                aout[base * 3 + 0] = p.x - cx;
                aout[base * 3 + 1] = p.y - cy;
                aout[base * 3 + 2] = p.z;
            }
            ++base;
        }
    }
}

// ---------------------------------------------------------------------------
extern "C" void kernel_launch(void* const* d_in, const int* in_sizes, int n_in,
                              void* d_out, int out_size) {
    const float* points  = (const float*)d_in[0];
    const float* anchors = (const float*)d_in[1];
    float* out = (float*)d_out;

    const int N = in_sizes[0] / 3;
    const int A = in_sizes[1] / 6;
    if (N <= 0 || A <= 0) return;

    // Derive n (and counts-tail presence) from out_size:
    //   out_size == A*(3n+1)  -> padded [A,n,3] followed by counts [A] (as float)
    //   out_size == A*3n      -> padded only
    int n = 512;
    int has_tail = 0;
    if (out_size % A == 0) {
        const int per = out_size / A;
        if (per % 3 == 0)            { n = per / 3;       has_tail = 0; }
        else if ((per - 1) % 3 == 0) { n = (per - 1) / 3; has_tail = 1; }
    } else {
        n = out_size / (A * 3);
    }
    if (n <= 0) return;

    int P = (N + CHUNK - 1) / CHUNK;
    if (P > MAX_P) P = MAX_P;                 // fixed problem sizes fit comfortably
    const int Npad = P * CHUNK;
    const long long zelems = (long long)A * n * 3;

    // 1) pack points + zero padded output
    prep_kernel<<<512, THREADS>>>(points, N, Npad, out, zelems);

    // 2) per-(chunk, anchor) counts
    dim3 grid(P, (A + THREADS - 1) / THREADS);
    count_kernel<<<grid, THREADS>>>(anchors, A);

    // 3) per-anchor exclusive prefix over chunks (+ clamped counts tail)
    prefix_kernel<<<(A + 255) / 256, 256>>>(A, P, n, out + zelems, has_tail);

    // 4) ordered scatter of matched points
    write_kernel<<<grid, THREADS>>>(anchors, A, n, out);
}